// round 1
// baseline (speedup 1.0000x reference)
#include <cuda_runtime.h>

#define BLOCK 128
#define TSEQ 200
#define OUTN 28

// ---- fast-but-accurate transcendentals (ex2/rcp approx: ~1e-6 rel err) ----
__device__ __forceinline__ float fexp2_(float x) {
    float y; asm("ex2.approx.f32 %0, %1;" : "=f"(y) : "f"(x)); return y;
}
__device__ __forceinline__ float frcp_(float x) {
    float y; asm("rcp.approx.f32 %0, %1;" : "=f"(y) : "f"(x)); return y;
}
// sigmoid(x) = 1 / (1 + 2^(-x*log2e))
__device__ __forceinline__ float sigm_(float x) {
    return frcp_(1.0f + fexp2_(-1.4426950408889634f * x));
}
// tanh(x) = 2 / (1 + 2^(-2x*log2e)) - 1
__device__ __forceinline__ float tanh_(float x) {
    return 2.0f * frcp_(1.0f + fexp2_(-2.8853900817779268f * x)) - 1.0f;
}

// smem layout (floats): Wout[22400] | W0[128] | W1[128] | B0[16] | B1[16] | Bout[28]
#define SM_WOUT 0
#define SM_W0   22400
#define SM_W1   22528
#define SM_B0   22656
#define SM_B1   22672
#define SM_BOUT 22688
#define SM_TOTAL_FLOATS 22716

__global__ void __launch_bounds__(BLOCK, 1) lstm_fused_kernel(
    const float* __restrict__ x,
    const float* __restrict__ Wih0, const float* __restrict__ Whh0,
    const float* __restrict__ bih0, const float* __restrict__ bhh0,
    const float* __restrict__ Wih1, const float* __restrict__ Whh1,
    const float* __restrict__ bih1, const float* __restrict__ bhh1,
    const float* __restrict__ Wout, const float* __restrict__ bout,
    float* __restrict__ out)
{
    extern __shared__ float sm[];
    const int tid = threadIdx.x;

    // ---- stage weights into shared memory ----
    {
        const float4* src = (const float4*)Wout;
        float4* dst = (float4*)(sm + SM_WOUT);
        #pragma unroll 4
        for (int i = tid; i < 22400 / 4; i += BLOCK) dst[i] = src[i];
    }
    if (tid < 64) {
        int g = tid >> 2, i = tid & 3;
        // per-gate layout: [ih0, ih1, ih2, ih3, hh0, hh1, hh2, hh3]
        sm[SM_W0 + g * 8 + i]     = Wih0[tid];
        sm[SM_W0 + g * 8 + 4 + i] = Whh0[tid];
        sm[SM_W1 + g * 8 + i]     = Wih1[tid];
        sm[SM_W1 + g * 8 + 4 + i] = Whh1[tid];
    }
    if (tid < 16) {
        sm[SM_B0 + tid] = bih0[tid] + bhh0[tid];
        sm[SM_B1 + tid] = bih1[tid] + bhh1[tid];
    }
    if (tid < OUTN) sm[SM_BOUT + tid] = bout[tid];
    __syncthreads();

    const int b = blockIdx.x * BLOCK + tid;  // one thread = one batch element
    const float4* xp = (const float4*)(x + (size_t)b * (TSEQ * 4));

    float h1[4] = {0.f, 0.f, 0.f, 0.f}, c1[4] = {0.f, 0.f, 0.f, 0.f};
    float h2[4] = {0.f, 0.f, 0.f, 0.f}, c2[4] = {0.f, 0.f, 0.f, 0.f};
    float acc[OUTN];
    #pragma unroll
    for (int o = 0; o < OUTN; o++) acc[o] = sm[SM_BOUT + o];

    // hoist biases into registers (32 regs, loop-invariant)
    float b0r[16], b1r[16];
    #pragma unroll
    for (int k = 0; k < 16; k++) { b0r[k] = sm[SM_B0 + k]; b1r[k] = sm[SM_B1 + k]; }

    #pragma unroll 1
    for (int t = 0; t < TSEQ; ++t) {
        const float4 xt = xp[t];

        // ---- layer 1: gates = xt @ Wih0^T + h1 @ Whh0^T + b ----
        float g[16];
        #pragma unroll
        for (int k = 0; k < 16; k++) {
            float4 wa = *(const float4*)(sm + SM_W0 + k * 8);
            float4 wb = *(const float4*)(sm + SM_W0 + k * 8 + 4);
            g[k] = b0r[k]
                 + xt.x * wa.x + xt.y * wa.y + xt.z * wa.z + xt.w * wa.w
                 + h1[0] * wb.x + h1[1] * wb.y + h1[2] * wb.z + h1[3] * wb.w;
        }
        #pragma unroll
        for (int j = 0; j < 4; j++) {
            float ig = sigm_(g[j]);
            float fg = sigm_(g[4 + j]);
            float gg = tanh_(g[8 + j]);
            float og = sigm_(g[12 + j]);
            c1[j] = fg * c1[j] + ig * gg;
            h1[j] = og * tanh_(c1[j]);
        }

        // ---- layer 2: gates = h1 @ Wih1^T + h2 @ Whh1^T + b ----
        #pragma unroll
        for (int k = 0; k < 16; k++) {
            float4 wa = *(const float4*)(sm + SM_W1 + k * 8);
            float4 wb = *(const float4*)(sm + SM_W1 + k * 8 + 4);
            g[k] = b1r[k]
                 + h1[0] * wa.x + h1[1] * wa.y + h1[2] * wa.z + h1[3] * wa.w
                 + h2[0] * wb.x + h2[1] * wb.y + h2[2] * wb.z + h2[3] * wb.w;
        }
        #pragma unroll
        for (int j = 0; j < 4; j++) {
            float ig = sigm_(g[j]);
            float fg = sigm_(g[4 + j]);
            float gg = tanh_(g[8 + j]);
            float og = sigm_(g[12 + j]);
            c2[j] = fg * c2[j] + ig * gg;
            h2[j] = og * tanh_(c2[j]);
        }

        // ---- output GEMV accumulate: acc[o] += h2 . Wout[o, t*4 : t*4+4] ----
        #pragma unroll
        for (int o = 0; o < OUTN; o++) {
            float4 w = *(const float4*)(sm + SM_WOUT + o * 800 + t * 4);
            acc[o] += h2[0] * w.x + h2[1] * w.y + h2[2] * w.z + h2[3] * w.w;
        }
    }

    float* op = out + (size_t)b * OUTN;
    #pragma unroll
    for (int o = 0; o < OUTN; o++) op[o] = acc[o];
}

extern "C" void kernel_launch(void* const* d_in, const int* in_sizes, int n_in,
                              void* d_out, int out_size)
{
    const float* x    = (const float*)d_in[0];
    const float* Wih0 = (const float*)d_in[1];
    const float* Whh0 = (const float*)d_in[2];
    const float* bih0 = (const float*)d_in[3];
    const float* bhh0 = (const float*)d_in[4];
    const float* Wih1 = (const float*)d_in[5];
    const float* Whh1 = (const float*)d_in[6];
    const float* bih1 = (const float*)d_in[7];
    const float* bhh1 = (const float*)d_in[8];
    const float* Wout = (const float*)d_in[9];
    const float* bout = (const float*)d_in[10];
    float* out = (float*)d_out;

    const int B = in_sizes[0] / (TSEQ * 4);   // 32768
    const int smem_bytes = SM_TOTAL_FLOATS * sizeof(float);  // 90864 B

    cudaFuncSetAttribute(lstm_fused_kernel,
                         cudaFuncAttributeMaxDynamicSharedMemorySize, smem_bytes);

    lstm_fused_kernel<<<B / BLOCK, BLOCK, smem_bytes>>>(
        x, Wih0, Whh0, bih0, bhh0, Wih1, Whh1, bih1, bhh1, Wout, bout, out);
}

// round 2
// speedup vs baseline: 1.0225x; 1.0225x over previous
#include <cuda_runtime.h>

#define BLOCK 128
#define TSEQ 200
#define OUTN 28

typedef unsigned long long u64;

// ---- fast-but-accurate transcendentals (ex2/rcp approx: ~1e-6 rel err) ----
__device__ __forceinline__ float fexp2_(float x) {
    float y; asm("ex2.approx.f32 %0, %1;" : "=f"(y) : "f"(x)); return y;
}
__device__ __forceinline__ float frcp_(float x) {
    float y; asm("rcp.approx.f32 %0, %1;" : "=f"(y) : "f"(x)); return y;
}
__device__ __forceinline__ float sigm_(float x) {
    return frcp_(1.0f + fexp2_(-1.4426950408889634f * x));
}
__device__ __forceinline__ float tanh_(float x) {
    return 2.0f * frcp_(1.0f + fexp2_(-2.8853900817779268f * x)) - 1.0f;
}

// ---- packed f32x2 ops (Blackwell: fma.rn.f32x2 only reachable via PTX) ----
__device__ __forceinline__ u64 fma2(u64 a, u64 b, u64 c) {
    u64 d; asm("fma.rn.f32x2 %0, %1, %2, %3;" : "=l"(d) : "l"(a), "l"(b), "l"(c));
    return d;
}
__device__ __forceinline__ u64 pack2(float lo, float hi) {
    u64 r; asm("mov.b64 %0, {%1, %2};" : "=l"(r) : "f"(lo), "f"(hi)); return r;
}
__device__ __forceinline__ void unpack2(float& lo, float& hi, u64 v) {
    asm("mov.b64 {%0, %1}, %2;" : "=f"(lo), "=f"(hi) : "l"(v));
}

// smem layout in u64 words:
//   WOUTP[800][14]  : packed Wout pairs {W[2o][c], W[2o+1][c]}
//   WP0/WP1[8][8]   : per gate-pair p, coefs 0-3 = ih, 4-7 = hh (packed over pair)
//   BP0/BP1[8]      : packed bias pairs
//   BOUTP[14]       : packed output-bias pairs
#define WOUTP 0
#define WP0   11200
#define WP1   11264
#define BP0   11328
#define BP1   11336
#define BOUTP 11344
#define SM_U64 11358   // 90864 bytes

__global__ void __launch_bounds__(BLOCK, 1) lstm_fused_kernel(
    const float* __restrict__ x,
    const float* __restrict__ Wih0, const float* __restrict__ Whh0,
    const float* __restrict__ bih0, const float* __restrict__ bhh0,
    const float* __restrict__ Wih1, const float* __restrict__ Whh1,
    const float* __restrict__ bih1, const float* __restrict__ bhh1,
    const float* __restrict__ Wout, const float* __restrict__ bout,
    float* __restrict__ out)
{
    extern __shared__ u64 smu[];
    const int tid = threadIdx.x;

    // ---- stage packed weights ----
    // Wout pairs: idx -> (o, c); consecutive tid -> consecutive c (coalesced LDG)
    for (int idx = tid; idx < 14 * 800; idx += BLOCK) {
        int o = idx / 800, c = idx - o * 800;
        smu[WOUTP + c * 14 + o] = pack2(Wout[(2 * o) * 800 + c],
                                        Wout[(2 * o + 1) * 800 + c]);
    }
    {   // 2 layers x 8 pairs x 8 coefs = 128 packs, one per thread
        int l = tid >> 6, r = tid & 63, p = r >> 3, i = r & 7;
        const float* Wih = l ? Wih1 : Wih0;
        const float* Whh = l ? Whh1 : Whh0;
        u64 v;
        if (i < 4) v = pack2(Wih[(2 * p) * 4 + i],       Wih[(2 * p + 1) * 4 + i]);
        else       v = pack2(Whh[(2 * p) * 4 + (i - 4)], Whh[(2 * p + 1) * 4 + (i - 4)]);
        smu[(l ? WP1 : WP0) + p * 8 + i] = v;
    }
    if (tid < 16) {
        int l = tid >> 3, p = tid & 7;
        const float* bi = l ? bih1 : bih0;
        const float* bh = l ? bhh1 : bhh0;
        smu[(l ? BP1 : BP0) + p] = pack2(bi[2 * p] + bh[2 * p],
                                         bi[2 * p + 1] + bh[2 * p + 1]);
    }
    if (tid < 14) smu[BOUTP + tid] = pack2(bout[2 * tid], bout[2 * tid + 1]);
    __syncthreads();

    const int b = blockIdx.x * BLOCK + tid;  // one thread = one batch element
    const float4* xp = (const float4*)(x + (size_t)b * (TSEQ * 4));

    float h1[4] = {0.f,0.f,0.f,0.f}, c1[4] = {0.f,0.f,0.f,0.f};
    float h2[4] = {0.f,0.f,0.f,0.f}, c2[4] = {0.f,0.f,0.f,0.f};

    u64 acc[14];
    #pragma unroll
    for (int o = 0; o < 14; o++) acc[o] = smu[BOUTP + o];

    const ulonglong2* w0 = (const ulonglong2*)(smu + WP0);
    const ulonglong2* w1 = (const ulonglong2*)(smu + WP1);
    const ulonglong2* wo = (const ulonglong2*)(smu + WOUTP);

    #pragma unroll 1
    for (int t = 0; t < TSEQ; ++t) {
        const float4 xt = xp[t];

        // ================= layer 1 =================
        {
            u64 u0 = pack2(xt.x, xt.x), u1 = pack2(xt.y, xt.y);
            u64 u2 = pack2(xt.z, xt.z), u3 = pack2(xt.w, xt.w);
            u64 v0 = pack2(h1[0], h1[0]), v1 = pack2(h1[1], h1[1]);
            u64 v2 = pack2(h1[2], h1[2]), v3 = pack2(h1[3], h1[3]);
            u64 g[8];
            #pragma unroll
            for (int p = 0; p < 8; p++) {
                ulonglong2 wa = w0[p * 4 + 0];   // ih coefs 0,1
                ulonglong2 wb = w0[p * 4 + 1];   // ih coefs 2,3
                ulonglong2 wc = w0[p * 4 + 2];   // hh coefs 0,1
                ulonglong2 wd = w0[p * 4 + 3];   // hh coefs 2,3
                u64 gp = smu[BP0 + p];
                gp = fma2(u0, wa.x, gp); gp = fma2(u1, wa.y, gp);
                gp = fma2(u2, wb.x, gp); gp = fma2(u3, wb.y, gp);
                gp = fma2(v0, wc.x, gp); gp = fma2(v1, wc.y, gp);
                gp = fma2(v2, wd.x, gp); gp = fma2(v3, wd.y, gp);
                g[p] = gp;
            }
            float gg[16];
            #pragma unroll
            for (int p = 0; p < 8; p++) unpack2(gg[2 * p], gg[2 * p + 1], g[p]);
            #pragma unroll
            for (int j = 0; j < 4; j++) {
                float ig = sigm_(gg[j]);
                float fg = sigm_(gg[4 + j]);
                float gt = tanh_(gg[8 + j]);
                float og = sigm_(gg[12 + j]);
                c1[j] = fg * c1[j] + ig * gt;
                h1[j] = og * tanh_(c1[j]);
            }
        }

        // ================= layer 2 =================
        {
            u64 u0 = pack2(h1[0], h1[0]), u1 = pack2(h1[1], h1[1]);
            u64 u2 = pack2(h1[2], h1[2]), u3 = pack2(h1[3], h1[3]);
            u64 v0 = pack2(h2[0], h2[0]), v1 = pack2(h2[1], h2[1]);
            u64 v2 = pack2(h2[2], h2[2]), v3 = pack2(h2[3], h2[3]);
            u64 g[8];
            #pragma unroll
            for (int p = 0; p < 8; p++) {
                ulonglong2 wa = w1[p * 4 + 0];
                ulonglong2 wb = w1[p * 4 + 1];
                ulonglong2 wc = w1[p * 4 + 2];
                ulonglong2 wd = w1[p * 4 + 3];
                u64 gp = smu[BP1 + p];
                gp = fma2(u0, wa.x, gp); gp = fma2(u1, wa.y, gp);
                gp = fma2(u2, wb.x, gp); gp = fma2(u3, wb.y, gp);
                gp = fma2(v0, wc.x, gp); gp = fma2(v1, wc.y, gp);
                gp = fma2(v2, wd.x, gp); gp = fma2(v3, wd.y, gp);
                g[p] = gp;
            }
            float gg[16];
            #pragma unroll
            for (int p = 0; p < 8; p++) unpack2(gg[2 * p], gg[2 * p + 1], g[p]);
            #pragma unroll
            for (int j = 0; j < 4; j++) {
                float ig = sigm_(gg[j]);
                float fg = sigm_(gg[4 + j]);
                float gt = tanh_(gg[8 + j]);
                float og = sigm_(gg[12 + j]);
                c2[j] = fg * c2[j] + ig * gt;
                h2[j] = og * tanh_(c2[j]);
            }
        }

        // ====== output GEMV: acc[pair] += h2[j] * Wout_pair[:, 4t+j] ======
        {
            u64 hp0 = pack2(h2[0], h2[0]), hp1 = pack2(h2[1], h2[1]);
            u64 hp2 = pack2(h2[2], h2[2]), hp3 = pack2(h2[3], h2[3]);
            #pragma unroll
            for (int j = 0; j < 4; j++) {
                u64 hp = (j == 0) ? hp0 : (j == 1) ? hp1 : (j == 2) ? hp2 : hp3;
                int c = 4 * t + j;
                #pragma unroll
                for (int q = 0; q < 7; q++) {
                    ulonglong2 wv = wo[c * 7 + q];
                    acc[2 * q]     = fma2(hp, wv.x, acc[2 * q]);
                    acc[2 * q + 1] = fma2(hp, wv.y, acc[2 * q + 1]);
                }
            }
        }
    }

    // packed pairs are bit-identical to the 28-float output row
    ulonglong2* op = (ulonglong2*)(out + (size_t)b * OUTN);
    #pragma unroll
    for (int q = 0; q < 7; q++) {
        ulonglong2 v; v.x = acc[2 * q]; v.y = acc[2 * q + 1];
        op[q] = v;
    }
}

extern "C" void kernel_launch(void* const* d_in, const int* in_sizes, int n_in,
                              void* d_out, int out_size)
{
    const float* x    = (const float*)d_in[0];
    const float* Wih0 = (const float*)d_in[1];
    const float* Whh0 = (const float*)d_in[2];
    const float* bih0 = (const float*)d_in[3];
    const float* bhh0 = (const float*)d_in[4];
    const float* Wih1 = (const float*)d_in[5];
    const float* Whh1 = (const float*)d_in[6];
    const float* bih1 = (const float*)d_in[7];
    const float* bhh1 = (const float*)d_in[8];
    const float* Wout = (const float*)d_in[9];
    const float* bout = (const float*)d_in[10];
    float* out = (float*)d_out;

    const int B = in_sizes[0] / (TSEQ * 4);              // 32768
    const int smem_bytes = SM_U64 * sizeof(u64);         // 90864 B

    cudaFuncSetAttribute(lstm_fused_kernel,
                         cudaFuncAttributeMaxDynamicSharedMemorySize, smem_bytes);

    lstm_fused_kernel<<<B / BLOCK, BLOCK, smem_bytes>>>(
        x, Wih0, Whh0, bih0, bhh0, Wih1, Whh1, bih1, bhh1, Wout, bout, out);
}

// round 3
// speedup vs baseline: 1.5433x; 1.5093x over previous
#include <cuda_runtime.h>

#define BLOCK 256
#define EPB   128       // batch elements per block (2 threads per element)
#define TSEQ  200

typedef unsigned long long u64;

// ---- exact-ish transcendentals (ex2/rcp approx: ~1e-6 rel err) ----
__device__ __forceinline__ float fexp2_(float x) {
    float y; asm("ex2.approx.f32 %0, %1;" : "=f"(y) : "f"(x)); return y;
}
__device__ __forceinline__ float frcp_(float x) {
    float y; asm("rcp.approx.f32 %0, %1;" : "=f"(y) : "f"(x)); return y;
}
__device__ __forceinline__ float sigm_(float x) {
    return frcp_(1.0f + fexp2_(-1.4426950408889634f * x));
}
__device__ __forceinline__ float tanh_(float x) {
    return 2.0f * frcp_(1.0f + fexp2_(-2.8853900817779268f * x)) - 1.0f;
}

// ---- packed f32x2 ops ----
__device__ __forceinline__ u64 fma2(u64 a, u64 b, u64 c) {
    u64 d; asm("fma.rn.f32x2 %0, %1, %2, %3;" : "=l"(d) : "l"(a), "l"(b), "l"(c));
    return d;
}
__device__ __forceinline__ u64 pack2(float lo, float hi) {
    u64 r; asm("mov.b64 %0, {%1, %2};" : "=l"(r) : "f"(lo), "f"(hi)); return r;
}
__device__ __forceinline__ void unpack2(float& lo, float& hi, u64 v) {
    asm("mov.b64 {%0, %1}, %2;" : "=f"(lo), "=f"(hi) : "l"(v));
}

// smem layout (u64 words):
//  WOUT [800 c][2 r][8 qpack]      : 12800  (qpack 7 is zero padding)
//  WG   [2 l][4 g][4 ip][2 r][2 e] : 128
#define WOUT_OFF 0
#define WG_OFF   12800
#define SM_U64   12928          // 103424 bytes

// one LSTM layer for the 2 hidden units owned by this thread
__device__ __forceinline__ void lstm_layer(
    const ulonglong2* __restrict__ wg, int r, const u64* __restrict__ bias,
    const u64* __restrict__ inp,          // 8 broadcast packs: 4 inputs + 4 h
    float& ca, float& cb, float& ha, float& hb)
{
    u64 gp[4];
    #pragma unroll
    for (int g = 0; g < 4; g++) {
        u64 a = bias[g];
        #pragma unroll
        for (int ip = 0; ip < 4; ip++) {
            ulonglong2 w = wg[g * 8 + ip * 2 + r];
            a = fma2(inp[2 * ip],     w.x, a);
            a = fma2(inp[2 * ip + 1], w.y, a);
        }
        gp[g] = a;
    }
    float iv0, iv1, fv0, fv1, gv0, gv1, ov0, ov1;
    unpack2(iv0, iv1, gp[0]); unpack2(fv0, fv1, gp[1]);
    unpack2(gv0, gv1, gp[2]); unpack2(ov0, ov1, gp[3]);
    float i0 = sigm_(iv0), f0 = sigm_(fv0), g0 = tanh_(gv0), o0 = sigm_(ov0);
    float i1 = sigm_(iv1), f1 = sigm_(fv1), g1 = tanh_(gv1), o1 = sigm_(ov1);
    ca = f0 * ca + i0 * g0;  ha = o0 * tanh_(ca);
    cb = f1 * cb + i1 * g1;  hb = o1 * tanh_(cb);
}

__global__ void __launch_bounds__(BLOCK, 2) lstm_fused_kernel(
    const float* __restrict__ x,
    const float* __restrict__ Wih0, const float* __restrict__ Whh0,
    const float* __restrict__ bih0, const float* __restrict__ bhh0,
    const float* __restrict__ Wih1, const float* __restrict__ Whh1,
    const float* __restrict__ bih1, const float* __restrict__ bhh1,
    const float* __restrict__ Wout, const float* __restrict__ bout,
    float* __restrict__ out)
{
    extern __shared__ u64 smu[];
    const int tid = threadIdx.x;
    const int r   = tid & 1;                       // which half of the element
    const int elem = blockIdx.x * EPB + (tid >> 1);

    // ---- stage Wout pairs: smu[c*16 + rr*8 + qp] = {W[14rr+2qp][c], W[14rr+2qp+1][c]} ----
    for (int idx = tid; idx < 12800; idx += BLOCK) {
        int c = idx >> 4, rr = (idx >> 3) & 1, qp = idx & 7;
        u64 v = 0;
        if (qp < 7) {
            int row = 14 * rr + 2 * qp;
            v = pack2(Wout[row * 800 + c], Wout[(row + 1) * 800 + c]);
        }
        smu[WOUT_OFF + idx] = v;
    }
    // ---- stage gate weights: per (l,g,in,r): pack over the 2 owned units ----
    if (tid < 128) {
        int l = tid >> 6, rest = tid & 63;
        int g = rest >> 4, in = (rest >> 1) & 7, rr = rest & 1;
        const float* Wih = l ? Wih1 : Wih0;
        const float* Whh = l ? Whh1 : Whh0;
        const float* src = (in < 4) ? Wih : Whh;
        int col = in & 3;
        int row0 = g * 4 + 2 * rr;
        u64 v = pack2(src[row0 * 4 + col], src[(row0 + 1) * 4 + col]);
        smu[WG_OFF + l * 64 + g * 16 + (in >> 1) * 4 + rr * 2 + (in & 1)] = v;
    }
    __syncthreads();

    const ulonglong2* wg0 = (const ulonglong2*)(smu + WG_OFF);
    const ulonglong2* wg1 = wg0 + 32;
    const ulonglong2* wo  = (const ulonglong2*)(smu + WOUT_OFF);

    // ---- biases (tiny, broadcast-cached in L1) ----
    u64 b0r[4], b1r[4];
    #pragma unroll
    for (int g = 0; g < 4; g++) {
        int k = g * 4 + 2 * r;
        b0r[g] = pack2(bih0[k] + bhh0[k], bih0[k + 1] + bhh0[k + 1]);
        b1r[g] = pack2(bih1[k] + bhh1[k], bih1[k + 1] + bhh1[k + 1]);
    }
    u64 acc[8];
    #pragma unroll
    for (int q = 0; q < 7; q++)
        acc[q] = pack2(bout[14 * r + 2 * q], bout[14 * r + 2 * q + 1]);
    acc[7] = 0;

    const float4* xp = (const float4*)(x + (size_t)elem * (TSEQ * 4));

    float h1f0 = 0.f, h1f1 = 0.f, h1f2 = 0.f, h1f3 = 0.f;
    float h2f0 = 0.f, h2f1 = 0.f, h2f2 = 0.f, h2f3 = 0.f;
    float c1a = 0.f, c1b = 0.f, c2a = 0.f, c2b = 0.f;

    #pragma unroll 1
    for (int t = 0; t < TSEQ; ++t) {
        const float4 xt = xp[t];

        // ---- layer 1 ----
        {
            u64 inp[8];
            inp[0] = pack2(xt.x, xt.x); inp[1] = pack2(xt.y, xt.y);
            inp[2] = pack2(xt.z, xt.z); inp[3] = pack2(xt.w, xt.w);
            inp[4] = pack2(h1f0, h1f0); inp[5] = pack2(h1f1, h1f1);
            inp[6] = pack2(h1f2, h1f2); inp[7] = pack2(h1f3, h1f3);
            float ha, hb;
            lstm_layer(wg0, r, b0r, inp, c1a, c1b, ha, hb);
            float oa = __shfl_xor_sync(0xffffffffu, ha, 1);
            float ob = __shfl_xor_sync(0xffffffffu, hb, 1);
            h1f0 = r ? oa : ha;  h1f1 = r ? ob : hb;
            h1f2 = r ? ha : oa;  h1f3 = r ? hb : ob;
        }
        // ---- layer 2 ----
        {
            u64 inp[8];
            inp[0] = pack2(h1f0, h1f0); inp[1] = pack2(h1f1, h1f1);
            inp[2] = pack2(h1f2, h1f2); inp[3] = pack2(h1f3, h1f3);
            inp[4] = pack2(h2f0, h2f0); inp[5] = pack2(h2f1, h2f1);
            inp[6] = pack2(h2f2, h2f2); inp[7] = pack2(h2f3, h2f3);
            float ha, hb;
            lstm_layer(wg1, r, b1r, inp, c2a, c2b, ha, hb);
            float oa = __shfl_xor_sync(0xffffffffu, ha, 1);
            float ob = __shfl_xor_sync(0xffffffffu, hb, 1);
            h2f0 = r ? oa : ha;  h2f1 = r ? ob : hb;
            h2f2 = r ? ha : oa;  h2f3 = r ? hb : ob;
        }
        // ---- GEMV: this thread's 14 outputs (+2 dummy), all 4 h2 values ----
        {
            const int cb = 4 * t;
            #pragma unroll
            for (int j = 0; j < 4; j++) {
                float hj = (j == 0) ? h2f0 : (j == 1) ? h2f1 : (j == 2) ? h2f2 : h2f3;
                u64 hp = pack2(hj, hj);
                const ulonglong2* wrow = wo + ((size_t)(cb + j) * 2 + r) * 4;
                #pragma unroll
                for (int q = 0; q < 4; q++) {
                    ulonglong2 wv = wrow[q];
                    acc[2 * q]     = fma2(hp, wv.x, acc[2 * q]);
                    acc[2 * q + 1] = fma2(hp, wv.y, acc[2 * q + 1]);
                }
            }
        }
    }

    // ---- write this thread's 14 outputs (acc[7] is dummy) ----
    u64* op = (u64*)(out + (size_t)elem * 28 + 14 * r);
    #pragma unroll
    for (int q = 0; q < 7; q++) op[q] = acc[q];
}

extern "C" void kernel_launch(void* const* d_in, const int* in_sizes, int n_in,
                              void* d_out, int out_size)
{
    const float* x    = (const float*)d_in[0];
    const float* Wih0 = (const float*)d_in[1];
    const float* Whh0 = (const float*)d_in[2];
    const float* bih0 = (const float*)d_in[3];
    const float* bhh0 = (const float*)d_in[4];
    const float* Wih1 = (const float*)d_in[5];
    const float* Whh1 = (const float*)d_in[6];
    const float* bih1 = (const float*)d_in[7];
    const float* bhh1 = (const float*)d_in[8];
    const float* Wout = (const float*)d_in[9];
    const float* bout = (const float*)d_in[10];
    float* out = (float*)d_out;

    const int B = in_sizes[0] / (TSEQ * 4);          // 32768
    const int smem_bytes = SM_U64 * sizeof(u64);     // 103424 B

    cudaFuncSetAttribute(lstm_fused_kernel,
                         cudaFuncAttributeMaxDynamicSharedMemorySize, smem_bytes);

    lstm_fused_kernel<<<B / EPB, BLOCK, smem_bytes>>>(
        x, Wih0, Whh0, bih0, bhh0, Wih1, Whh1, bih1, bhh1, Wout, bout, out);
}

// round 4
// speedup vs baseline: 2.0294x; 1.3150x over previous
#include <cuda_runtime.h>

#define BLOCK 256
#define EPB   64        // elements per block (4 threads per element)
#define TSEQ  200

typedef unsigned long long u64;

// ---- tanh.approx-based activations (MUFU.TANH: ~1.4e-5 abs err) ----
__device__ __forceinline__ float tanha_(float x) {
    float y; asm("tanh.approx.f32 %0, %1;" : "=f"(y) : "f"(x)); return y;
}
__device__ __forceinline__ float sigm_(float x) {
    return fmaf(tanha_(0.5f * x), 0.5f, 0.5f);
}

// ---- packed f32x2 ops ----
__device__ __forceinline__ u64 fma2(u64 a, u64 b, u64 c) {
    u64 d; asm("fma.rn.f32x2 %0, %1, %2, %3;" : "=l"(d) : "l"(a), "l"(b), "l"(c));
    return d;
}
__device__ __forceinline__ u64 pack2(float lo, float hi) {
    u64 r; asm("mov.b64 %0, {%1, %2};" : "=l"(r) : "f"(lo), "f"(hi)); return r;
}
__device__ __forceinline__ void unpack2(float& lo, float& hi, u64 v) {
    asm("mov.b64 {%0, %1}, %2;" : "=f"(lo), "=f"(hi) : "l"(v));
}

// smem: Wout packs only. Layout [800 phys-col][4 r][4 qpack] u64 = 12800 u64 = 100 KB.
// Column permutation per r-class baked in at staging: phys col (4t+s) holds the
// weights of logical column 4t + (s^r) for r-class r (slot s carries unit r^s).
#define SM_U64 12800

// one LSTM unit step: returns h for the unit owned by this thread
__device__ __forceinline__ float unit_step(
    const u64* __restrict__ inp,   // 8 broadcast packs
    const u64* __restrict__ wIF, const u64* __restrict__ wGO,
    u64 bIF, u64 bGO, float& c)
{
    u64 gIF = bIF, gGO = bGO;
    #pragma unroll
    for (int in = 0; in < 8; in++) {
        gIF = fma2(inp[in], wIF[in], gIF);
        gGO = fma2(inp[in], wGO[in], gGO);
    }
    float iv, fv, gv, ov;
    unpack2(iv, fv, gIF);
    unpack2(gv, ov, gGO);
    float i = sigm_(iv), f = sigm_(fv), g = tanha_(gv), o = sigm_(ov);
    c = f * c + i * g;
    return o * tanha_(c);
}

__global__ void __launch_bounds__(BLOCK, 2) lstm_fused_kernel(
    const float* __restrict__ x,
    const float* __restrict__ Wih0, const float* __restrict__ Whh0,
    const float* __restrict__ bih0, const float* __restrict__ bhh0,
    const float* __restrict__ Wih1, const float* __restrict__ Whh1,
    const float* __restrict__ bih1, const float* __restrict__ bhh1,
    const float* __restrict__ Wout, const float* __restrict__ bout,
    float* __restrict__ out)
{
    extern __shared__ u64 smu[];
    const int tid  = threadIdx.x;
    const int r    = tid & 3;                     // unit index / output quarter
    const int elem = blockIdx.x * EPB + (tid >> 2);

    // ---- stage Wout packs with per-r column permutation ----
    for (int idx = tid; idx < SM_U64; idx += BLOCK) {
        int c  = idx >> 4;
        int r4 = (idx >> 2) & 3;
        int q  = idx & 3;
        int srcc = (c & ~3) | ((c & 3) ^ r4);     // logical column for this r-class
        int row0 = 7 * r4 + 2 * q;                // rows 7r .. 7r+6 (q=3 hi is dummy)
        float lo = Wout[row0 * 800 + srcc];
        float hi = (q < 3) ? Wout[(row0 + 1) * 800 + srcc] : 0.0f;
        smu[idx] = pack2(lo, hi);
    }
    __syncthreads();

    // ---- gate weights -> registers (slot s of h-inputs carries unit r^s) ----
    u64 wIF0[8], wGO0[8], wIF1[8], wGO1[8];
    #pragma unroll
    for (int in = 0; in < 4; in++) {
        int cs = r ^ in;                           // permuted column for h slots
        wIF0[in]     = pack2(Wih0[(0  + r) * 4 + in], Wih0[(4  + r) * 4 + in]);
        wGO0[in]     = pack2(Wih0[(8  + r) * 4 + in], Wih0[(12 + r) * 4 + in]);
        wIF0[4 + in] = pack2(Whh0[(0  + r) * 4 + cs], Whh0[(4  + r) * 4 + cs]);
        wGO0[4 + in] = pack2(Whh0[(8  + r) * 4 + cs], Whh0[(12 + r) * 4 + cs]);
        wIF1[in]     = pack2(Wih1[(0  + r) * 4 + cs], Wih1[(4  + r) * 4 + cs]);
        wGO1[in]     = pack2(Wih1[(8  + r) * 4 + cs], Wih1[(12 + r) * 4 + cs]);
        wIF1[4 + in] = pack2(Whh1[(0  + r) * 4 + cs], Whh1[(4  + r) * 4 + cs]);
        wGO1[4 + in] = pack2(Whh1[(8  + r) * 4 + cs], Whh1[(12 + r) * 4 + cs]);
    }
    const u64 bIF0 = pack2(bih0[r] + bhh0[r],           bih0[4 + r]  + bhh0[4 + r]);
    const u64 bGO0 = pack2(bih0[8 + r] + bhh0[8 + r],   bih0[12 + r] + bhh0[12 + r]);
    const u64 bIF1 = pack2(bih1[r] + bhh1[r],           bih1[4 + r]  + bhh1[4 + r]);
    const u64 bGO1 = pack2(bih1[8 + r] + bhh1[8 + r],   bih1[12 + r] + bhh1[12 + r]);

    u64 acc[4];
    #pragma unroll
    for (int q = 0; q < 4; q++)
        acc[q] = pack2(bout[7 * r + 2 * q], (q < 3) ? bout[7 * r + 2 * q + 1] : 0.0f);

    const float4* xp = (const float4*)(x + (size_t)elem * (TSEQ * 4));
    const ulonglong2* wop = (const ulonglong2*)smu + (size_t)r * 2;

    float h1s[4] = {0.f, 0.f, 0.f, 0.f};          // slot s = unit r^s
    float h2s[4] = {0.f, 0.f, 0.f, 0.f};
    float c1 = 0.f, c2 = 0.f;

    #pragma unroll 1
    for (int t = 0; t < TSEQ; ++t) {
        const float4 xt = xp[t];

        // ---- layer 1 ----
        u64 inp[8];
        inp[0] = pack2(xt.x, xt.x); inp[1] = pack2(xt.y, xt.y);
        inp[2] = pack2(xt.z, xt.z); inp[3] = pack2(xt.w, xt.w);
        inp[4] = pack2(h1s[0], h1s[0]); inp[5] = pack2(h1s[1], h1s[1]);
        inp[6] = pack2(h1s[2], h1s[2]); inp[7] = pack2(h1s[3], h1s[3]);
        float h1 = unit_step(inp, wIF0, wGO0, bIF0, bGO0, c1);
        {
            float a1 = __shfl_xor_sync(0xffffffffu, h1, 1);
            float a2 = __shfl_xor_sync(0xffffffffu, h1, 2);
            float a3 = __shfl_xor_sync(0xffffffffu, a1, 2);
            h1s[0] = h1; h1s[1] = a1; h1s[2] = a2; h1s[3] = a3;
        }

        // ---- layer 2 ----
        inp[0] = pack2(h1s[0], h1s[0]); inp[1] = pack2(h1s[1], h1s[1]);
        inp[2] = pack2(h1s[2], h1s[2]); inp[3] = pack2(h1s[3], h1s[3]);
        inp[4] = pack2(h2s[0], h2s[0]); inp[5] = pack2(h2s[1], h2s[1]);
        inp[6] = pack2(h2s[2], h2s[2]); inp[7] = pack2(h2s[3], h2s[3]);
        float h2 = unit_step(inp, wIF1, wGO1, bIF1, bGO1, c2);
        {
            float a1 = __shfl_xor_sync(0xffffffffu, h2, 1);
            float a2 = __shfl_xor_sync(0xffffffffu, h2, 2);
            float a3 = __shfl_xor_sync(0xffffffffu, a1, 2);
            h2s[0] = h2; h2s[1] = a1; h2s[2] = a2; h2s[3] = a3;
        }

        // ---- GEMV: 7 outputs (+1 dummy lane) for this thread ----
        #pragma unroll
        for (int s = 0; s < 4; s++) {
            u64 hp = pack2(h2s[s], h2s[s]);
            const ulonglong2* wrow = wop + (size_t)(4 * t + s) * 8;
            ulonglong2 w0 = wrow[0];
            ulonglong2 w1 = wrow[1];
            acc[0] = fma2(hp, w0.x, acc[0]);
            acc[1] = fma2(hp, w0.y, acc[1]);
            acc[2] = fma2(hp, w1.x, acc[2]);
            acc[3] = fma2(hp, w1.y, acc[3]);
        }
    }

    // ---- write 7 outputs ----
    float* op = out + (size_t)elem * 28 + 7 * r;
    float o0, o1, o2, o3, o4, o5, o6, dummy;
    unpack2(o0, o1, acc[0]); unpack2(o2, o3, acc[1]);
    unpack2(o4, o5, acc[2]); unpack2(o6, dummy, acc[3]);
    op[0] = o0; op[1] = o1; op[2] = o2; op[3] = o3;
    op[4] = o4; op[5] = o5; op[6] = o6;
}

extern "C" void kernel_launch(void* const* d_in, const int* in_sizes, int n_in,
                              void* d_out, int out_size)
{
    const float* x    = (const float*)d_in[0];
    const float* Wih0 = (const float*)d_in[1];
    const float* Whh0 = (const float*)d_in[2];
    const float* bih0 = (const float*)d_in[3];
    const float* bhh0 = (const float*)d_in[4];
    const float* Wih1 = (const float*)d_in[5];
    const float* Whh1 = (const float*)d_in[6];
    const float* bih1 = (const float*)d_in[7];
    const float* bhh1 = (const float*)d_in[8];
    const float* Wout = (const float*)d_in[9];
    const float* bout = (const float*)d_in[10];
    float* out = (float*)d_out;

    const int B = in_sizes[0] / (TSEQ * 4);          // 32768
    const int smem_bytes = SM_U64 * sizeof(u64);     // 102400 B

    cudaFuncSetAttribute(lstm_fused_kernel,
                         cudaFuncAttributeMaxDynamicSharedMemorySize, smem_bytes);

    lstm_fused_kernel<<<B / EPB, BLOCK, smem_bytes>>>(
        x, Wih0, Whh0, bih0, bhh0, Wih1, Whh1, bih1, bhh1, Wout, bout, out);
}

// round 5
// speedup vs baseline: 2.4220x; 1.1935x over previous
#include <cuda_runtime.h>

#define BLOCK 256
#define EPB   64        // elements per block (4 threads per element)
#define TSEQ  200

typedef unsigned long long u64;

// ---- tanh.approx-based activations (MUFU.TANH: ~1.4e-5 abs err) ----
__device__ __forceinline__ float tanha_(float x) {
    float y; asm("tanh.approx.f32 %0, %1;" : "=f"(y) : "f"(x)); return y;
}
__device__ __forceinline__ float sigm_(float x) {
    return fmaf(tanha_(0.5f * x), 0.5f, 0.5f);
}

// ---- packed f32x2 ops ----
__device__ __forceinline__ u64 fma2(u64 a, u64 b, u64 c) {
    u64 d; asm("fma.rn.f32x2 %0, %1, %2, %3;" : "=l"(d) : "l"(a), "l"(b), "l"(c));
    return d;
}
__device__ __forceinline__ u64 pack2(float lo, float hi) {
    u64 r; asm("mov.b64 %0, {%1, %2};" : "=l"(r) : "f"(lo), "f"(hi)); return r;
}
__device__ __forceinline__ void unpack2(float& lo, float& hi, u64 v) {
    asm("mov.b64 {%0, %1}, %2;" : "=f"(lo), "=f"(hi) : "l"(v));
}

// smem: Wout packs. [800 phys-col][4 r][4 qpack] u64 = 12800 u64 = 100 KB.
// phys col (4t+s) for r-class r holds logical column 4t + (s^r) (slot s = unit r^s).
#define SM_U64 12800

// one LSTM unit step: returns h for the unit owned by this thread
__device__ __forceinline__ float unit_step(
    const u64* __restrict__ inp,   // 8 broadcast packs
    const u64* __restrict__ wIF, const u64* __restrict__ wGO,
    u64 bIF, u64 bGO, float& c)
{
    u64 gIF = bIF, gGO = bGO;
    #pragma unroll
    for (int in = 0; in < 8; in++) {
        gIF = fma2(inp[in], wIF[in], gIF);
        gGO = fma2(inp[in], wGO[in], gGO);
    }
    float iv, fv, gv, ov;
    unpack2(iv, fv, gIF);
    unpack2(gv, ov, gGO);
    float i = sigm_(iv), f = sigm_(fv), g = tanha_(gv), o = sigm_(ov);
    c = f * c + i * g;
    return o * tanha_(c);
}

__global__ void __launch_bounds__(BLOCK, 2) lstm_fused_kernel(
    const float* __restrict__ x,
    const float* __restrict__ Wih0, const float* __restrict__ Whh0,
    const float* __restrict__ bih0, const float* __restrict__ bhh0,
    const float* __restrict__ Wih1, const float* __restrict__ Whh1,
    const float* __restrict__ bih1, const float* __restrict__ bhh1,
    const float* __restrict__ Wout, const float* __restrict__ bout,
    float* __restrict__ out)
{
    extern __shared__ u64 smu[];
    const int tid  = threadIdx.x;
    const int r    = tid & 3;                     // unit index / output quarter
    const int elem = blockIdx.x * EPB + (tid >> 2);

    // ---- stage Wout packs with per-r column permutation ----
    for (int idx = tid; idx < SM_U64; idx += BLOCK) {
        int c  = idx >> 4;
        int r4 = (idx >> 2) & 3;
        int q  = idx & 3;
        int srcc = (c & ~3) | ((c & 3) ^ r4);     // logical column for this r-class
        int row0 = 7 * r4 + 2 * q;                // rows 7r .. 7r+6 (q=3 hi is dummy)
        float lo = Wout[row0 * 800 + srcc];
        float hi = (q < 3) ? Wout[(row0 + 1) * 800 + srcc] : 0.0f;
        smu[idx] = pack2(lo, hi);
    }
    __syncthreads();

    // ---- gate weights -> registers (slot s of h-inputs carries unit r^s) ----
    u64 wIF0[8], wGO0[8], wIF1[8], wGO1[8];
    #pragma unroll
    for (int in = 0; in < 4; in++) {
        int cs = r ^ in;                           // permuted column for h slots
        wIF0[in]     = pack2(Wih0[(0  + r) * 4 + in], Wih0[(4  + r) * 4 + in]);
        wGO0[in]     = pack2(Wih0[(8  + r) * 4 + in], Wih0[(12 + r) * 4 + in]);
        wIF0[4 + in] = pack2(Whh0[(0  + r) * 4 + cs], Whh0[(4  + r) * 4 + cs]);
        wGO0[4 + in] = pack2(Whh0[(8  + r) * 4 + cs], Whh0[(12 + r) * 4 + cs]);
        wIF1[in]     = pack2(Wih1[(0  + r) * 4 + cs], Wih1[(4  + r) * 4 + cs]);
        wGO1[in]     = pack2(Wih1[(8  + r) * 4 + cs], Wih1[(12 + r) * 4 + cs]);
        wIF1[4 + in] = pack2(Whh1[(0  + r) * 4 + cs], Whh1[(4  + r) * 4 + cs]);
        wGO1[4 + in] = pack2(Whh1[(8  + r) * 4 + cs], Whh1[(12 + r) * 4 + cs]);
    }
    const u64 bIF0 = pack2(bih0[r] + bhh0[r],           bih0[4 + r]  + bhh0[4 + r]);
    const u64 bGO0 = pack2(bih0[8 + r] + bhh0[8 + r],   bih0[12 + r] + bhh0[12 + r]);
    const u64 bIF1 = pack2(bih1[r] + bhh1[r],           bih1[4 + r]  + bhh1[4 + r]);
    const u64 bGO1 = pack2(bih1[8 + r] + bhh1[8 + r],   bih1[12 + r] + bhh1[12 + r]);

    u64 acc[4];
    #pragma unroll
    for (int q = 0; q < 4; q++)
        acc[q] = pack2(bout[7 * r + 2 * q], (q < 3) ? bout[7 * r + 2 * q + 1] : 0.0f);

    const float4* xp = (const float4*)(x + (size_t)elem * (TSEQ * 4));
    const ulonglong2* wop = (const ulonglong2*)smu + (size_t)r * 2;

    float h1s[4] = {0.f, 0.f, 0.f, 0.f};          // slot s = unit r^s
    float h2s[4] = {0.f, 0.f, 0.f, 0.f};
    float c1 = 0.f, c2 = 0.f;

    #pragma unroll 1
    for (int tg = 0; tg < TSEQ; tg += 4) {
        // group-preloaded x: 4 independent LDGs (MLP=4), one L1 line per group
        float4 xg[4];
        xg[0] = xp[tg + 0]; xg[1] = xp[tg + 1];
        xg[2] = xp[tg + 2]; xg[3] = xp[tg + 3];

        #pragma unroll
        for (int u = 0; u < 4; u++) {
            const int t = tg + u;
            const float4 xt = xg[u];

            // ---- layer 1 ----
            u64 inp[8];
            inp[0] = pack2(xt.x, xt.x); inp[1] = pack2(xt.y, xt.y);
            inp[2] = pack2(xt.z, xt.z); inp[3] = pack2(xt.w, xt.w);
            inp[4] = pack2(h1s[0], h1s[0]); inp[5] = pack2(h1s[1], h1s[1]);
            inp[6] = pack2(h1s[2], h1s[2]); inp[7] = pack2(h1s[3], h1s[3]);
            float h1 = unit_step(inp, wIF0, wGO0, bIF0, bGO0, c1);
            {   // parallel butterfly: three independent shuffles
                float a1 = __shfl_xor_sync(0xffffffffu, h1, 1);
                float a2 = __shfl_xor_sync(0xffffffffu, h1, 2);
                float a3 = __shfl_xor_sync(0xffffffffu, h1, 3);
                h1s[0] = h1; h1s[1] = a1; h1s[2] = a2; h1s[3] = a3;
            }

            // ---- layer 2 ----
            inp[0] = pack2(h1s[0], h1s[0]); inp[1] = pack2(h1s[1], h1s[1]);
            inp[2] = pack2(h1s[2], h1s[2]); inp[3] = pack2(h1s[3], h1s[3]);
            inp[4] = pack2(h2s[0], h2s[0]); inp[5] = pack2(h2s[1], h2s[1]);
            inp[6] = pack2(h2s[2], h2s[2]); inp[7] = pack2(h2s[3], h2s[3]);
            float h2 = unit_step(inp, wIF1, wGO1, bIF1, bGO1, c2);
            {
                float a1 = __shfl_xor_sync(0xffffffffu, h2, 1);
                float a2 = __shfl_xor_sync(0xffffffffu, h2, 2);
                float a3 = __shfl_xor_sync(0xffffffffu, h2, 3);
                h2s[0] = h2; h2s[1] = a1; h2s[2] = a2; h2s[3] = a3;
            }

            // ---- GEMV: 7 outputs (+1 dummy lane) for this thread ----
            // off the recurrence critical path; unroll lets ptxas sink it
            #pragma unroll
            for (int s = 0; s < 4; s++) {
                u64 hp = pack2(h2s[s], h2s[s]);
                const ulonglong2* wrow = wop + (size_t)(4 * t + s) * 8;
                ulonglong2 w0 = wrow[0];
                ulonglong2 w1 = wrow[1];
                acc[0] = fma2(hp, w0.x, acc[0]);
                acc[1] = fma2(hp, w0.y, acc[1]);
                acc[2] = fma2(hp, w1.x, acc[2]);
                acc[3] = fma2(hp, w1.y, acc[3]);
            }
        }
    }

    // ---- write 7 outputs ----
    float* op = out + (size_t)elem * 28 + 7 * r;
    float o0, o1, o2, o3, o4, o5, o6, dummy;
    unpack2(o0, o1, acc[0]); unpack2(o2, o3, acc[1]);
    unpack2(o4, o5, acc[2]); unpack2(o6, dummy, acc[3]);
    op[0] = o0; op[1] = o1; op[2] = o2; op[3] = o3;
    op[4] = o4; op[5] = o5; op[6] = o6;
}

extern "C" void kernel_launch(void* const* d_in, const int* in_sizes, int n_in,
                              void* d_out, int out_size)
{
    const float* x    = (const float*)d_in[0];
    const float* Wih0 = (const float*)d_in[1];
    const float* Whh0 = (const float*)d_in[2];
    const float* bih0 = (const float*)d_in[3];
    const float* bhh0 = (const float*)d_in[4];
    const float* Wih1 = (const float*)d_in[5];
    const float* Whh1 = (const float*)d_in[6];
    const float* bih1 = (const float*)d_in[7];
    const float* bhh1 = (const float*)d_in[8];
    const float* Wout = (const float*)d_in[9];
    const float* bout = (const float*)d_in[10];
    float* out = (float*)d_out;

    const int B = in_sizes[0] / (TSEQ * 4);          // 32768
    const int smem_bytes = SM_U64 * sizeof(u64);     // 102400 B

    cudaFuncSetAttribute(lstm_fused_kernel,
                         cudaFuncAttributeMaxDynamicSharedMemorySize, smem_bytes);

    lstm_fused_kernel<<<B / EPB, BLOCK, smem_bytes>>>(
        x, Wih0, Whh0, bih0, bhh0, Wih1, Whh1, bih1, bhh1, Wout, bout, out);
}